// round 4
// baseline (speedup 1.0000x reference)
#include <cuda_runtime.h>

#define Bn 8
#define Dn 192
#define Ln 4096
#define Nn 16
#define Rn 6
#define Cn 38
#define Kn 4
#define NC 32
#define Lc 128

// scratch (allocation-free device globals)
__device__ float g_DU[(size_t)Bn*Kn*Ln*Dn*2];        // (bk,l,d,{dt,u})
__device__ float g_BC[(size_t)Bn*Kn*Ln*Nn*2];        // (bk,l,n,{B,C})
__device__ float g_ys[(size_t)Bn*Kn*Ln*Dn];          // (bk,l,d)
__device__ float g_hend[(size_t)Bn*Kn*NC*Dn*Nn];     // (bk,c,d,n)
__device__ float g_S[(size_t)Bn*Kn*NC*Dn];           // (bk,c,d)

__device__ __forceinline__ float ex2f(float x){
    float r; asm("ex2.approx.ftz.f32 %0, %1;" : "=f"(r) : "f"(x)); return r;
}
__device__ __forceinline__ float lg2f(float x){
    float r; asm("lg2.approx.ftz.f32 %0, %1;" : "=f"(r) : "f"(x)); return r;
}

// ---------------------------------------------------------------------------
// Kernel A: cross-scan gather + x_proj + dt_proj + softplus. (R2 config)
// ---------------------------------------------------------------------------
__global__ __launch_bounds__(256, 3) void proj_kernel(
    const float* __restrict__ x, const float* __restrict__ xpw,
    const float* __restrict__ dtw, const float* __restrict__ dtb)
{
    __shared__ float xt[Dn*32];        // xt[d][j]
    __shared__ float dts_s[Rn][32];

    const int bid = blockIdx.x;
    const int t   = bid & 127;
    const int k   = (bid >> 7) & 3;
    const int b   = bid >> 9;
    const int tid = threadIdx.x;

    int l0, lstep, p0, pstep;
    if (k == 0)      { l0 = t*32; lstep = 1;  p0 = t*32;        pstep = 1;  }
    else if (k == 2) { l0 = t*32; lstep = 1;  p0 = 4095 - t*32; pstep = -1; }
    else {
        int h = t & 63, w0 = (t >> 6) * 32;
        p0 = h*64 + w0; pstep = 1;
        if (k == 1) { l0 = w0*64 + h;          lstep = 64;  }
        else        { l0 = 4095 - (w0*64 + h); lstep = -64; }
    }

    const float* xb = x + (size_t)b*Dn*Ln;
    for (int idx = tid; idx < Dn*32; idx += 256) {
        int d = idx >> 5, j = idx & 31;
        xt[idx] = xb[(size_t)d*Ln + p0 + j*pstep];
    }
    __syncthreads();

    {
        const int j = tid & 31;
        const int w = tid >> 5;
        const int l = l0 + j*lstep;
        const size_t bkl = (size_t)(b*Kn + k)*Ln + l;

        float acc[5] = {0.f,0.f,0.f,0.f,0.f};
        const float4* wp[5];
        #pragma unroll
        for (int m = 0; m < 5; m++) {
            int c = w + 8*m; if (c > Cn-1) c = Cn-1;
            wp[m] = (const float4*)(xpw + (size_t)(k*Cn + c)*Dn);
        }
        #pragma unroll 2
        for (int i = 0; i < Dn/4; i++) {
            float x0 = xt[(4*i+0)*32 + j];
            float x1 = xt[(4*i+1)*32 + j];
            float x2 = xt[(4*i+2)*32 + j];
            float x3 = xt[(4*i+3)*32 + j];
            #pragma unroll
            for (int m = 0; m < 5; m++) {
                float4 wv = wp[m][i];
                acc[m] = fmaf(wv.x, x0, acc[m]);
                acc[m] = fmaf(wv.y, x1, acc[m]);
                acc[m] = fmaf(wv.z, x2, acc[m]);
                acc[m] = fmaf(wv.w, x3, acc[m]);
            }
        }
        #pragma unroll
        for (int m = 0; m < 5; m++) {
            int c = w + 8*m;
            if (c < Rn) dts_s[c][j] = acc[m];
            else if (c < Cn) {
                int n = c - Rn, half = 0;
                if (n >= Nn) { n -= Nn; half = 1; }
                g_BC[(bkl*Nn + n)*2 + half] = acc[m];
            }
        }
    }
    __syncthreads();

    for (int idx = tid; idx < Dn*32; idx += 256) {
        int d = idx % Dn, j = idx / Dn;
        float acc = dtb[k*Dn + d];
        #pragma unroll
        for (int r = 0; r < Rn; r++) acc = fmaf(dts_s[r][j], dtw[(k*Dn + d)*Rn + r], acc);
        float e = ex2f(acc * 1.4426950408889634f);
        float sp = 0.6931471805599453f * lg2f(1.f + e);
        if (acc > 20.f) sp = acc;
        float u = xt[d*32 + j];
        int l = l0 + j*lstep;
        size_t o = ((size_t)(b*Kn + k)*Ln + l)*Dn + d;
        ((float2*)g_DU)[o] = make_float2(sp, u);
    }
}

// ---------------------------------------------------------------------------
// Scan pass 1 (split-state): 384 threads; lane&15 -> channel offset,
// lane>>4 -> state half (8 states each). A,h in registers.
// ---------------------------------------------------------------------------
__global__ __launch_bounds__(384, 3) void scan_p1(const float* __restrict__ A_logs)
{
    __shared__ float4 sBC[Lc*8];
    const int bk   = blockIdx.x >> 5;
    const int c    = blockIdx.x & 31;
    const int tid  = threadIdx.x;
    const int warp = tid >> 5;
    const int lane = tid & 31;
    const int d    = warp*16 + (lane & 15);
    const int half = lane >> 4;
    const int k    = bk & 3;

    const float4* gbc = (const float4*)(g_BC + ((size_t)bk*Ln + (size_t)c*Lc)*32);
    for (int i = tid; i < Lc*8; i += 384) sBC[i] = gbc[i];
    __syncthreads();

    float A[8];
    {
        const float4* al = (const float4*)(A_logs + ((size_t)(k*Dn + d)*16 + half*8));
        #pragma unroll
        for (int m = 0; m < 2; m++) {
            float4 v = al[m];
            A[4*m+0] = -expf(v.x) * 1.4426950408889634f;
            A[4*m+1] = -expf(v.y) * 1.4426950408889634f;
            A[4*m+2] = -expf(v.z) * 1.4426950408889634f;
            A[4*m+3] = -expf(v.w) * 1.4426950408889634f;
        }
    }

    float h[8];
    #pragma unroll
    for (int n = 0; n < 8; n++) h[n] = 0.f;
    float S = 0.f;
    const float2* du = ((const float2*)g_DU) + ((size_t)bk*Ln + (size_t)c*Lc)*Dn + d;
    const float4* bcrow = sBC + half*4;

    for (int t = 0; t < Lc; t++) {
        float2 duv = du[(size_t)t*Dn];
        float dt = duv.x, dtu = dt*duv.y;
        S += dt;
        #pragma unroll
        for (int m = 0; m < 4; m++) {
            float4 q = bcrow[t*8 + m];
            h[2*m]   = fmaf(ex2f(dt*A[2*m]),   h[2*m],   dtu*q.x);
            h[2*m+1] = fmaf(ex2f(dt*A[2*m+1]), h[2*m+1], dtu*q.z);
        }
    }
    float4* out = (float4*)(g_hend + (((size_t)bk*NC + c)*Dn + d)*16 + half*8);
    out[0] = make_float4(h[0], h[1], h[2], h[3]);
    out[1] = make_float4(h[4], h[5], h[6], h[7]);
    if (half == 0) g_S[((size_t)bk*NC + c)*Dn + d] = S;
}

// ---------------------------------------------------------------------------
// Scan mid: chain chunk summaries -> exclusive h_init prefix (in place).
// ---------------------------------------------------------------------------
__global__ __launch_bounds__(256) void scan_mid(const float* __restrict__ A_logs)
{
    int gid = blockIdx.x*256 + threadIdx.x;
    if (gid >= 32*Dn*Nn) return;
    int n  = gid & 15;
    int d  = (gid >> 4) % Dn;
    int bk = gid / (Dn*16);
    int k  = bk & 3;
    float A = -expf(A_logs[(size_t)(k*Dn + d)*16 + n]) * 1.4426950408889634f;
    float h = 0.f;
    for (int c = 0; c < NC; c++) {
        size_t o = (((size_t)bk*NC + c)*Dn + d)*16 + n;
        float hend = g_hend[o];
        float S = g_S[((size_t)bk*NC + c)*Dn + d];
        g_hend[o] = h;
        h = fmaf(ex2f(A*S), h, hend);
    }
}

// ---------------------------------------------------------------------------
// Scan pass 2 (split-state): rescan from h_init; y via 1 shfl; coalesced out.
// ---------------------------------------------------------------------------
__global__ __launch_bounds__(384, 3) void scan_p2(
    const float* __restrict__ A_logs, const float* __restrict__ Ds)
{
    __shared__ float4 sBC[Lc*8];
    const int bk   = blockIdx.x >> 5;
    const int c    = blockIdx.x & 31;
    const int tid  = threadIdx.x;
    const int warp = tid >> 5;
    const int lane = tid & 31;
    const int d    = warp*16 + (lane & 15);
    const int half = lane >> 4;
    const int k    = bk & 3;

    const float4* gbc = (const float4*)(g_BC + ((size_t)bk*Ln + (size_t)c*Lc)*32);
    for (int i = tid; i < Lc*8; i += 384) sBC[i] = gbc[i];
    __syncthreads();

    float A[8];
    {
        const float4* al = (const float4*)(A_logs + ((size_t)(k*Dn + d)*16 + half*8));
        #pragma unroll
        for (int m = 0; m < 2; m++) {
            float4 v = al[m];
            A[4*m+0] = -expf(v.x) * 1.4426950408889634f;
            A[4*m+1] = -expf(v.y) * 1.4426950408889634f;
            A[4*m+2] = -expf(v.z) * 1.4426950408889634f;
            A[4*m+3] = -expf(v.w) * 1.4426950408889634f;
        }
    }

    float h[8];
    {
        const float4* hin = (const float4*)(g_hend + (((size_t)bk*NC + c)*Dn + d)*16 + half*8);
        float4 v0 = hin[0], v1 = hin[1];
        h[0]=v0.x; h[1]=v0.y; h[2]=v0.z; h[3]=v0.w;
        h[4]=v1.x; h[5]=v1.y; h[6]=v1.z; h[7]=v1.w;
    }
    const float Dd = Ds[k*Dn + d];

    const float2* du = ((const float2*)g_DU) + ((size_t)bk*Ln + (size_t)c*Lc)*Dn + d;
    float* yo = g_ys + ((size_t)bk*Ln + (size_t)c*Lc)*Dn + d;
    const float4* bcrow = sBC + half*4;

    for (int t = 0; t < Lc; t++) {
        float2 duv = du[(size_t)t*Dn];
        float dt = duv.x, u = duv.y, dtu = dt*u;
        float pa = 0.f, pb = 0.f;
        #pragma unroll
        for (int m = 0; m < 4; m++) {
            float4 q = bcrow[t*8 + m];
            h[2*m]   = fmaf(ex2f(dt*A[2*m]),   h[2*m],   dtu*q.x);
            h[2*m+1] = fmaf(ex2f(dt*A[2*m+1]), h[2*m+1], dtu*q.z);
            pa = fmaf(h[2*m],   q.y, pa);
            pb = fmaf(h[2*m+1], q.w, pb);
        }
        float p = pa + pb;
        p += __shfl_xor_sync(0xffffffffu, p, 16);
        if (half == 0) yo[(size_t)t*Dn] = fmaf(Dd, u, p);
    }
}

// ---------------------------------------------------------------------------
// CrossMerge + LayerNorm.
// ---------------------------------------------------------------------------
__global__ __launch_bounds__(256) void merge_ln_kernel(
    const float* __restrict__ gamma, const float* __restrict__ beta,
    float* __restrict__ out)
{
    const int bid  = blockIdx.x;
    const int b    = bid >> 9;
    const int l    = ((bid & 511) << 3) + (threadIdx.x >> 5);
    const int lane = threadIdx.x & 31;
    const int hh = l >> 6, ww = l & 63;
    const int lT = ww*64 + hh;

    const float* y0 = g_ys + ((size_t)(b*4+0)*Ln + l)*Dn;
    const float* y1 = g_ys + ((size_t)(b*4+1)*Ln + lT)*Dn;
    const float* y2 = g_ys + ((size_t)(b*4+2)*Ln + (4095 - l))*Dn;
    const float* y3 = g_ys + ((size_t)(b*4+3)*Ln + (4095 - lT))*Dn;

    float v[6]; float s = 0.f;
    #pragma unroll
    for (int i = 0; i < 6; i++) {
        int dd = lane + 32*i;
        v[i] = y0[dd] + y1[dd] + y2[dd] + y3[dd];
        s += v[i];
    }
    #pragma unroll
    for (int o = 16; o; o >>= 1) s += __shfl_xor_sync(0xffffffffu, s, o);
    float mean = s * (1.f/192.f);
    float var = 0.f;
    #pragma unroll
    for (int i = 0; i < 6; i++) { float z = v[i] - mean; var = fmaf(z, z, var); }
    #pragma unroll
    for (int o = 16; o; o >>= 1) var += __shfl_xor_sync(0xffffffffu, var, o);
    float rstd = rsqrtf(var*(1.f/192.f) + 1e-5f);

    size_t ob = ((size_t)b*Ln + l)*Dn;
    #pragma unroll
    for (int i = 0; i < 6; i++) {
        int dd = lane + 32*i;
        out[ob + dd] = fmaf((v[i] - mean)*rstd, gamma[dd], beta[dd]);
    }
}

extern "C" void kernel_launch(void* const* d_in, const int* in_sizes, int n_in,
                              void* d_out, int out_size) {
    const float* x    = (const float*)d_in[0];
    const float* xpw  = (const float*)d_in[1];
    const float* dtw  = (const float*)d_in[2];
    const float* dtb  = (const float*)d_in[3];
    const float* Alog = (const float*)d_in[4];
    const float* Ds   = (const float*)d_in[5];
    const float* gam  = (const float*)d_in[6];
    const float* bet  = (const float*)d_in[7];
    float* out = (float*)d_out;

    proj_kernel<<<Bn*Kn*128, 256>>>(x, xpw, dtw, dtb);
    scan_p1<<<32*NC, 384>>>(Alog);
    scan_mid<<<(32*Dn*Nn + 255)/256, 256>>>(Alog);
    scan_p2<<<32*NC, 384>>>(Alog, Ds);
    merge_ln_kernel<<<Bn*512, 256>>>(gam, bet, out);
}

// round 5
// speedup vs baseline: 1.2662x; 1.2662x over previous
#include <cuda_runtime.h>

#define Bn 8
#define Dn 192
#define Ln 4096
#define Nn 16
#define Rn 6
#define Cn 38
#define Kn 4
#define NC 32
#define Lc 128

// scratch (allocation-free device globals); DU padded 4 steps for prefetch ring
__device__ float g_DU[(size_t)Bn*Kn*Ln*Dn*2 + Dn*8];
__device__ float g_BC[(size_t)Bn*Kn*Ln*Nn*2];
__device__ float g_ys[(size_t)Bn*Kn*Ln*Dn];
__device__ float g_hend[(size_t)Bn*Kn*NC*Dn*Nn];
__device__ float g_S[(size_t)Bn*Kn*NC*Dn];

__device__ __forceinline__ float ex2f(float x){
    float r; asm("ex2.approx.ftz.f32 %0, %1;" : "=f"(r) : "f"(x)); return r;
}
__device__ __forceinline__ float lg2f(float x){
    float r; asm("lg2.approx.ftz.f32 %0, %1;" : "=f"(r) : "f"(x)); return r;
}

// ---------------------------------------------------------------------------
// Kernel A: cross-scan gather + x_proj + dt_proj + softplus. (R2 config)
// ---------------------------------------------------------------------------
__global__ __launch_bounds__(256, 3) void proj_kernel(
    const float* __restrict__ x, const float* __restrict__ xpw,
    const float* __restrict__ dtw, const float* __restrict__ dtb)
{
    __shared__ float xt[Dn*32];
    __shared__ float dts_s[Rn][32];

    const int bid = blockIdx.x;
    const int t   = bid & 127;
    const int k   = (bid >> 7) & 3;
    const int b   = bid >> 9;
    const int tid = threadIdx.x;

    int l0, lstep, p0, pstep;
    if (k == 0)      { l0 = t*32; lstep = 1;  p0 = t*32;        pstep = 1;  }
    else if (k == 2) { l0 = t*32; lstep = 1;  p0 = 4095 - t*32; pstep = -1; }
    else {
        int h = t & 63, w0 = (t >> 6) * 32;
        p0 = h*64 + w0; pstep = 1;
        if (k == 1) { l0 = w0*64 + h;          lstep = 64;  }
        else        { l0 = 4095 - (w0*64 + h); lstep = -64; }
    }

    const float* xb = x + (size_t)b*Dn*Ln;
    for (int idx = tid; idx < Dn*32; idx += 256) {
        int d = idx >> 5, j = idx & 31;
        xt[idx] = xb[(size_t)d*Ln + p0 + j*pstep];
    }
    __syncthreads();

    {
        const int j = tid & 31;
        const int w = tid >> 5;
        const int l = l0 + j*lstep;
        const size_t bkl = (size_t)(b*Kn + k)*Ln + l;

        float acc[5] = {0.f,0.f,0.f,0.f,0.f};
        const float4* wp[5];
        #pragma unroll
        for (int m = 0; m < 5; m++) {
            int c = w + 8*m; if (c > Cn-1) c = Cn-1;
            wp[m] = (const float4*)(xpw + (size_t)(k*Cn + c)*Dn);
        }
        #pragma unroll 2
        for (int i = 0; i < Dn/4; i++) {
            float x0 = xt[(4*i+0)*32 + j];
            float x1 = xt[(4*i+1)*32 + j];
            float x2 = xt[(4*i+2)*32 + j];
            float x3 = xt[(4*i+3)*32 + j];
            #pragma unroll
            for (int m = 0; m < 5; m++) {
                float4 wv = wp[m][i];
                acc[m] = fmaf(wv.x, x0, acc[m]);
                acc[m] = fmaf(wv.y, x1, acc[m]);
                acc[m] = fmaf(wv.z, x2, acc[m]);
                acc[m] = fmaf(wv.w, x3, acc[m]);
            }
        }
        #pragma unroll
        for (int m = 0; m < 5; m++) {
            int c = w + 8*m;
            if (c < Rn) dts_s[c][j] = acc[m];
            else if (c < Cn) {
                int n = c - Rn, half = 0;
                if (n >= Nn) { n -= Nn; half = 1; }
                g_BC[(bkl*Nn + n)*2 + half] = acc[m];
            }
        }
    }
    __syncthreads();

    for (int idx = tid; idx < Dn*32; idx += 256) {
        int d = idx % Dn, j = idx / Dn;
        float acc = dtb[k*Dn + d];
        #pragma unroll
        for (int r = 0; r < Rn; r++) acc = fmaf(dts_s[r][j], dtw[(k*Dn + d)*Rn + r], acc);
        float e = ex2f(acc * 1.4426950408889634f);
        float sp = 0.6931471805599453f * lg2f(1.f + e);
        if (acc > 20.f) sp = acc;
        float u = xt[d*32 + j];
        int l = l0 + j*lstep;
        size_t o = ((size_t)(b*Kn + k)*Ln + l)*Dn + d;
        ((float2*)g_DU)[o] = make_float2(sp, u);
    }
}

// ---------------------------------------------------------------------------
// Scan pass 1: lane=channel, A/h in regs, 4-deep DU prefetch ring,
// EX2 for step t+1 hoisted to end of iteration t (off the h critical path).
// ---------------------------------------------------------------------------
__global__ __launch_bounds__(192, 4) void scan_p1(const float* __restrict__ A_logs)
{
    __shared__ float4 sBC[Lc*8];
    const int bk = blockIdx.x >> 5;
    const int c  = blockIdx.x & 31;
    const int d  = threadIdx.x;
    const int k  = bk & 3;

    const float4* gbc = (const float4*)(g_BC + ((size_t)bk*Ln + (size_t)c*Lc)*32);
    for (int i = d; i < Lc*8; i += 192) sBC[i] = gbc[i];
    __syncthreads();

    float A[16];
    {
        const float4* al = (const float4*)(A_logs + (size_t)(k*Dn + d)*16);
        #pragma unroll
        for (int m = 0; m < 4; m++) {
            float4 v = al[m];
            A[4*m+0] = -expf(v.x) * 1.4426950408889634f;
            A[4*m+1] = -expf(v.y) * 1.4426950408889634f;
            A[4*m+2] = -expf(v.z) * 1.4426950408889634f;
            A[4*m+3] = -expf(v.w) * 1.4426950408889634f;
        }
    }

    float h[16];
    #pragma unroll
    for (int n = 0; n < 16; n++) h[n] = 0.f;
    float S = 0.f;

    const float2* du = ((const float2*)g_DU) + ((size_t)bk*Ln + (size_t)c*Lc)*Dn + d;
    float2 ring[4];
    #pragma unroll
    for (int i = 0; i < 4; i++) ring[i] = du[(size_t)i*Dn];
    du += 4*Dn;

    float dA[16];
    #pragma unroll
    for (int n = 0; n < 16; n++) dA[n] = ex2f(ring[0].x * A[n]);

    #pragma unroll 4
    for (int t = 0; t < Lc; t++) {
        float2 cur = ring[t & 3];
        ring[t & 3] = du[0]; du += Dn;          // prefetch t+4 (pad-safe)
        float dt = cur.x, dtu = dt*cur.y;
        S += dt;
        #pragma unroll
        for (int m = 0; m < 8; m++) {
            float4 q = sBC[t*8 + m];
            h[2*m]   = fmaf(dA[2*m],   h[2*m],   dtu*q.x);
            h[2*m+1] = fmaf(dA[2*m+1], h[2*m+1], dtu*q.z);
        }
        float dtn = ring[(t+1) & 3].x;          // step t+1 already resident
        #pragma unroll
        for (int n = 0; n < 16; n++) dA[n] = ex2f(dtn * A[n]);
    }

    float4* out = (float4*)(g_hend + (((size_t)bk*NC + c)*Dn + d)*16);
    #pragma unroll
    for (int m = 0; m < 4; m++) out[m] = make_float4(h[4*m], h[4*m+1], h[4*m+2], h[4*m+3]);
    g_S[((size_t)bk*NC + c)*Dn + d] = S;
}

// ---------------------------------------------------------------------------
// Scan mid: chain chunk summaries -> exclusive h_init prefix (in place).
// ---------------------------------------------------------------------------
__global__ __launch_bounds__(256) void scan_mid(const float* __restrict__ A_logs)
{
    int gid = blockIdx.x*256 + threadIdx.x;
    if (gid >= 32*Dn*Nn) return;
    int n  = gid & 15;
    int d  = (gid >> 4) % Dn;
    int bk = gid / (Dn*16);
    int k  = bk & 3;
    float A = -expf(A_logs[(size_t)(k*Dn + d)*16 + n]) * 1.4426950408889634f;
    float h = 0.f;
    for (int c = 0; c < NC; c++) {
        size_t o = (((size_t)bk*NC + c)*Dn + d)*16 + n;
        float hend = g_hend[o];
        float S = g_S[((size_t)bk*NC + c)*Dn + d];
        g_hend[o] = h;
        h = fmaf(ex2f(A*S), h, hend);
    }
}

// ---------------------------------------------------------------------------
// Scan pass 2: same structure as p1 + y emission in (bk,l,d) layout.
// ---------------------------------------------------------------------------
__global__ __launch_bounds__(192, 4) void scan_p2(
    const float* __restrict__ A_logs, const float* __restrict__ Ds)
{
    __shared__ float4 sBC[Lc*8];
    const int bk = blockIdx.x >> 5;
    const int c  = blockIdx.x & 31;
    const int d  = threadIdx.x;
    const int k  = bk & 3;

    const float4* gbc = (const float4*)(g_BC + ((size_t)bk*Ln + (size_t)c*Lc)*32);
    for (int i = d; i < Lc*8; i += 192) sBC[i] = gbc[i];
    __syncthreads();

    float A[16];
    {
        const float4* al = (const float4*)(A_logs + (size_t)(k*Dn + d)*16);
        #pragma unroll
        for (int m = 0; m < 4; m++) {
            float4 v = al[m];
            A[4*m+0] = -expf(v.x) * 1.4426950408889634f;
            A[4*m+1] = -expf(v.y) * 1.4426950408889634f;
            A[4*m+2] = -expf(v.z) * 1.4426950408889634f;
            A[4*m+3] = -expf(v.w) * 1.4426950408889634f;
        }
    }

    float h[16];
    {
        const float4* hin = (const float4*)(g_hend + (((size_t)bk*NC + c)*Dn + d)*16);
        #pragma unroll
        for (int m = 0; m < 4; m++) {
            float4 v = hin[m];
            h[4*m+0] = v.x; h[4*m+1] = v.y; h[4*m+2] = v.z; h[4*m+3] = v.w;
        }
    }
    const float Dd = Ds[k*Dn + d];

    const float2* du = ((const float2*)g_DU) + ((size_t)bk*Ln + (size_t)c*Lc)*Dn + d;
    float* yo = g_ys + ((size_t)bk*Ln + (size_t)c*Lc)*Dn + d;

    float2 ring[4];
    #pragma unroll
    for (int i = 0; i < 4; i++) ring[i] = du[(size_t)i*Dn];
    du += 4*Dn;

    float dA[16];
    #pragma unroll
    for (int n = 0; n < 16; n++) dA[n] = ex2f(ring[0].x * A[n]);

    #pragma unroll 4
    for (int t = 0; t < Lc; t++) {
        float2 cur = ring[t & 3];
        ring[t & 3] = du[0]; du += Dn;
        float dt = cur.x, u = cur.y, dtu = dt*u;
        float pa = 0.f, pb = 0.f;
        #pragma unroll
        for (int m = 0; m < 8; m++) {
            float4 q = sBC[t*8 + m];
            h[2*m]   = fmaf(dA[2*m],   h[2*m],   dtu*q.x);
            h[2*m+1] = fmaf(dA[2*m+1], h[2*m+1], dtu*q.z);
            pa = fmaf(h[2*m],   q.y, pa);
            pb = fmaf(h[2*m+1], q.w, pb);
        }
        yo[(size_t)t*Dn] = fmaf(Dd, u, pa + pb);
        float dtn = ring[(t+1) & 3].x;
        #pragma unroll
        for (int n = 0; n < 16; n++) dA[n] = ex2f(dtn * A[n]);
    }
}

// ---------------------------------------------------------------------------
// CrossMerge + LayerNorm.
// ---------------------------------------------------------------------------
__global__ __launch_bounds__(256) void merge_ln_kernel(
    const float* __restrict__ gamma, const float* __restrict__ beta,
    float* __restrict__ out)
{
    const int bid  = blockIdx.x;
    const int b    = bid >> 9;
    const int l    = ((bid & 511) << 3) + (threadIdx.x >> 5);
    const int lane = threadIdx.x & 31;
    const int hh = l >> 6, ww = l & 63;
    const int lT = ww*64 + hh;

    const float* y0 = g_ys + ((size_t)(b*4+0)*Ln + l)*Dn;
    const float* y1 = g_ys + ((size_t)(b*4+1)*Ln + lT)*Dn;
    const float* y2 = g_ys + ((size_t)(b*4+2)*Ln + (4095 - l))*Dn;
    const float* y3 = g_ys + ((size_t)(b*4+3)*Ln + (4095 - lT))*Dn;

    float v[6]; float s = 0.f;
    #pragma unroll
    for (int i = 0; i < 6; i++) {
        int dd = lane + 32*i;
        v[i] = y0[dd] + y1[dd] + y2[dd] + y3[dd];
        s += v[i];
    }
    #pragma unroll
    for (int o = 16; o; o >>= 1) s += __shfl_xor_sync(0xffffffffu, s, o);
    float mean = s * (1.f/192.f);
    float var = 0.f;
    #pragma unroll
    for (int i = 0; i < 6; i++) { float z = v[i] - mean; var = fmaf(z, z, var); }
    #pragma unroll
    for (int o = 16; o; o >>= 1) var += __shfl_xor_sync(0xffffffffu, var, o);
    float rstd = rsqrtf(var*(1.f/192.f) + 1e-5f);

    size_t ob = ((size_t)b*Ln + l)*Dn;
    #pragma unroll
    for (int i = 0; i < 6; i++) {
        int dd = lane + 32*i;
        out[ob + dd] = fmaf((v[i] - mean)*rstd, gamma[dd], beta[dd]);
    }
}

extern "C" void kernel_launch(void* const* d_in, const int* in_sizes, int n_in,
                              void* d_out, int out_size) {
    const float* x    = (const float*)d_in[0];
    const float* xpw  = (const float*)d_in[1];
    const float* dtw  = (const float*)d_in[2];
    const float* dtb  = (const float*)d_in[3];
    const float* Alog = (const float*)d_in[4];
    const float* Ds   = (const float*)d_in[5];
    const float* gam  = (const float*)d_in[6];
    const float* bet  = (const float*)d_in[7];
    float* out = (float*)d_out;

    proj_kernel<<<Bn*Kn*128, 256>>>(x, xpw, dtw, dtb);
    scan_p1<<<32*NC, 192>>>(Alog);
    scan_mid<<<(32*Dn*Nn + 255)/256, 256>>>(Alog);
    scan_p2<<<32*NC, 192>>>(Alog, Ds);
    merge_ln_kernel<<<Bn*512, 256>>>(gam, bet, out);
}

// round 6
// speedup vs baseline: 1.3996x; 1.1053x over previous
#include <cuda_runtime.h>

#define Bn 8
#define Dn 192
#define Ln 4096
#define Nn 16
#define Rn 6
#define Cn 38
#define Kn 4
#define NC 32
#define Lc 128

// scratch (allocation-free device globals); DU padded 4 steps for prefetch ring
__device__ float g_DU[(size_t)Bn*Kn*Ln*Dn*2 + Dn*8];
__device__ float g_B [(size_t)Bn*Kn*Ln*Nn];
__device__ float g_C [(size_t)Bn*Kn*Ln*Nn];
__device__ float g_ys[(size_t)Bn*Kn*Ln*Dn];
__device__ float g_hend[(size_t)Bn*Kn*NC*Dn*Nn];
__device__ float g_S[(size_t)Bn*Kn*NC*Dn];

__device__ __forceinline__ float ex2f(float x){
    float r; asm("ex2.approx.ftz.f32 %0, %1;" : "=f"(r) : "f"(x)); return r;
}
__device__ __forceinline__ float lg2f(float x){
    float r; asm("lg2.approx.ftz.f32 %0, %1;" : "=f"(r) : "f"(x)); return r;
}

// ---------------------------------------------------------------------------
// Kernel A: cross-scan gather + x_proj + dt_proj + softplus.
// 64-position tiles; each thread: 5 channels x 2 positions (halved weight LDG).
// ---------------------------------------------------------------------------
__global__ __launch_bounds__(256, 3) void proj_kernel(
    const float* __restrict__ x, const float* __restrict__ xpw,
    const float* __restrict__ dtw, const float* __restrict__ dtb)
{
    __shared__ float xt[Dn*64];        // xt[d][j], j=0..63
    __shared__ float dts_s[Rn][64];

    const int bid = blockIdx.x;        // 2048 = 8*4*64
    const int t   = bid & 63;
    const int k   = (bid >> 6) & 3;
    const int b   = bid >> 8;
    const int tid = threadIdx.x;

    // gather source: p(j). k=0,1,3: p = t*64 + j ; k=2: p = 4095 - t*64 - j
    int p0, pstep;
    if (k == 2) { p0 = 4095 - t*64; pstep = -1; }
    else        { p0 = t*64;        pstep = 1;  }

    const float* xb = x + (size_t)b*Dn*Ln;
    for (int idx = tid; idx < Dn*64; idx += 256) {
        int d = idx >> 6, j = idx & 63;
        xt[idx] = xb[(size_t)d*Ln + p0 + j*pstep];
    }
    __syncthreads();

    // output position l(j)
    auto lof = [&](int j) -> int {
        if (k == 1) return j*64 + t;
        if (k == 3) return 4095 - j*64 - t;
        return t*64 + j;
    };

    {
        const int j = tid & 31;        // positions j and j+32
        const int w = tid >> 5;
        const int la = lof(j), lb_ = lof(j+32);
        const size_t bkla = (size_t)(b*Kn + k)*Ln + la;
        const size_t bklb = (size_t)(b*Kn + k)*Ln + lb_;

        float acc[5][2];
        #pragma unroll
        for (int m = 0; m < 5; m++) { acc[m][0] = 0.f; acc[m][1] = 0.f; }
        const float4* wp[5];
        #pragma unroll
        for (int m = 0; m < 5; m++) {
            int c = w + 8*m; if (c > Cn-1) c = Cn-1;
            wp[m] = (const float4*)(xpw + (size_t)(k*Cn + c)*Dn);
        }
        #pragma unroll 2
        for (int i = 0; i < Dn/4; i++) {
            float a0 = xt[(4*i+0)*64 + j],  b0 = xt[(4*i+0)*64 + j+32];
            float a1 = xt[(4*i+1)*64 + j],  b1 = xt[(4*i+1)*64 + j+32];
            float a2 = xt[(4*i+2)*64 + j],  b2 = xt[(4*i+2)*64 + j+32];
            float a3 = xt[(4*i+3)*64 + j],  b3 = xt[(4*i+3)*64 + j+32];
            #pragma unroll
            for (int m = 0; m < 5; m++) {
                float4 wv = wp[m][i];
                acc[m][0] = fmaf(wv.x, a0, acc[m][0]);
                acc[m][1] = fmaf(wv.x, b0, acc[m][1]);
                acc[m][0] = fmaf(wv.y, a1, acc[m][0]);
                acc[m][1] = fmaf(wv.y, b1, acc[m][1]);
                acc[m][0] = fmaf(wv.z, a2, acc[m][0]);
                acc[m][1] = fmaf(wv.z, b2, acc[m][1]);
                acc[m][0] = fmaf(wv.w, a3, acc[m][0]);
                acc[m][1] = fmaf(wv.w, b3, acc[m][1]);
            }
        }
        #pragma unroll
        for (int m = 0; m < 5; m++) {
            int c = w + 8*m;
            if (c < Rn) { dts_s[c][j] = acc[m][0]; dts_s[c][j+32] = acc[m][1]; }
            else if (c < Cn) {
                int n = c - Rn;
                if (n < Nn) { g_B[bkla*Nn + n] = acc[m][0]; g_B[bklb*Nn + n] = acc[m][1]; }
                else        { n -= Nn;
                              g_C[bkla*Nn + n] = acc[m][0]; g_C[bklb*Nn + n] = acc[m][1]; }
            }
        }
    }
    __syncthreads();

    // delta = softplus(dt_w @ dts + bias); store (delta,u) interleaved
    for (int idx = tid; idx < Dn*64; idx += 256) {
        int d = idx % Dn, j = idx / Dn;
        float acc = dtb[k*Dn + d];
        #pragma unroll
        for (int r = 0; r < Rn; r++) acc = fmaf(dts_s[r][j], dtw[(k*Dn + d)*Rn + r], acc);
        float e = ex2f(acc * 1.4426950408889634f);
        float sp = 0.6931471805599453f * lg2f(1.f + e);
        if (acc > 20.f) sp = acc;
        float u = xt[d*64 + j];
        int l = lof(j);
        size_t o = ((size_t)(b*Kn + k)*Ln + l)*Dn + d;
        ((float2*)g_DU)[o] = make_float2(sp, u);
    }
}

// ---------------------------------------------------------------------------
// Scan pass 1: lane=channel, A/h/dA in regs, ring-4 DU prefetch, hoisted EX2.
// Stages only B (4 LDS.128/step).
// ---------------------------------------------------------------------------
__global__ __launch_bounds__(192, 4) void scan_p1(const float* __restrict__ A_logs)
{
    __shared__ float4 sB[Lc*4];
    const int bk = blockIdx.x >> 5;
    const int c  = blockIdx.x & 31;
    const int d  = threadIdx.x;
    const int k  = bk & 3;

    const float4* gb = (const float4*)(g_B + ((size_t)bk*Ln + (size_t)c*Lc)*16);
    for (int i = d; i < Lc*4; i += 192) sB[i] = gb[i];
    __syncthreads();

    float A[16];
    {
        const float4* al = (const float4*)(A_logs + (size_t)(k*Dn + d)*16);
        #pragma unroll
        for (int m = 0; m < 4; m++) {
            float4 v = al[m];
            A[4*m+0] = -expf(v.x) * 1.4426950408889634f;
            A[4*m+1] = -expf(v.y) * 1.4426950408889634f;
            A[4*m+2] = -expf(v.z) * 1.4426950408889634f;
            A[4*m+3] = -expf(v.w) * 1.4426950408889634f;
        }
    }

    float h[16];
    #pragma unroll
    for (int n = 0; n < 16; n++) h[n] = 0.f;
    float S = 0.f;

    const float2* du = ((const float2*)g_DU) + ((size_t)bk*Ln + (size_t)c*Lc)*Dn + d;
    float2 ring[4];
    #pragma unroll
    for (int i = 0; i < 4; i++) ring[i] = du[(size_t)i*Dn];
    du += 4*Dn;

    float dA[16];
    #pragma unroll
    for (int n = 0; n < 16; n++) dA[n] = ex2f(ring[0].x * A[n]);

    #pragma unroll 4
    for (int t = 0; t < Lc; t++) {
        float2 cur = ring[t & 3];
        ring[t & 3] = du[0]; du += Dn;
        float dt = cur.x, dtu = dt*cur.y;
        S += dt;
        #pragma unroll
        for (int m = 0; m < 4; m++) {
            float4 q = sB[t*4 + m];
            h[4*m+0] = fmaf(dA[4*m+0], h[4*m+0], dtu*q.x);
            h[4*m+1] = fmaf(dA[4*m+1], h[4*m+1], dtu*q.y);
            h[4*m+2] = fmaf(dA[4*m+2], h[4*m+2], dtu*q.z);
            h[4*m+3] = fmaf(dA[4*m+3], h[4*m+3], dtu*q.w);
        }
        float dtn = ring[(t+1) & 3].x;
        #pragma unroll
        for (int n = 0; n < 16; n++) dA[n] = ex2f(dtn * A[n]);
    }

    float4* out = (float4*)(g_hend + (((size_t)bk*NC + c)*Dn + d)*16);
    #pragma unroll
    for (int m = 0; m < 4; m++) out[m] = make_float4(h[4*m], h[4*m+1], h[4*m+2], h[4*m+3]);
    g_S[((size_t)bk*NC + c)*Dn + d] = S;
}

// ---------------------------------------------------------------------------
// Scan mid: chain chunk summaries -> exclusive h_init prefix (in place).
// ---------------------------------------------------------------------------
__global__ __launch_bounds__(256) void scan_mid(const float* __restrict__ A_logs)
{
    int gid = blockIdx.x*256 + threadIdx.x;
    if (gid >= 32*Dn*Nn) return;
    int n  = gid & 15;
    int d  = (gid >> 4) % Dn;
    int bk = gid / (Dn*16);
    int k  = bk & 3;
    float A = -expf(A_logs[(size_t)(k*Dn + d)*16 + n]) * 1.4426950408889634f;
    float h = 0.f;
    for (int c = 0; c < NC; c++) {
        size_t o = (((size_t)bk*NC + c)*Dn + d)*16 + n;
        float hend = g_hend[o];
        float S = g_S[((size_t)bk*NC + c)*Dn + d];
        g_hend[o] = h;
        h = fmaf(ex2f(A*S), h, hend);
    }
}

// ---------------------------------------------------------------------------
// Scan pass 2: rescan from h_init, emit y (bk,l,d). Stages B and C.
// ---------------------------------------------------------------------------
__global__ __launch_bounds__(192, 4) void scan_p2(
    const float* __restrict__ A_logs, const float* __restrict__ Ds)
{
    __shared__ float4 sB[Lc*4];
    __shared__ float4 sC[Lc*4];
    const int bk = blockIdx.x >> 5;
    const int c  = blockIdx.x & 31;
    const int d  = threadIdx.x;
    const int k  = bk & 3;

    const float4* gb = (const float4*)(g_B + ((size_t)bk*Ln + (size_t)c*Lc)*16);
    const float4* gc = (const float4*)(g_C + ((size_t)bk*Ln + (size_t)c*Lc)*16);
    for (int i = d; i < Lc*4; i += 192) { sB[i] = gb[i]; sC[i] = gc[i]; }
    __syncthreads();

    float A[16];
    {
        const float4* al = (const float4*)(A_logs + (size_t)(k*Dn + d)*16);
        #pragma unroll
        for (int m = 0; m < 4; m++) {
            float4 v = al[m];
            A[4*m+0] = -expf(v.x) * 1.4426950408889634f;
            A[4*m+1] = -expf(v.y) * 1.4426950408889634f;
            A[4*m+2] = -expf(v.z) * 1.4426950408889634f;
            A[4*m+3] = -expf(v.w) * 1.4426950408889634f;
        }
    }

    float h[16];
    {
        const float4* hin = (const float4*)(g_hend + (((size_t)bk*NC + c)*Dn + d)*16);
        #pragma unroll
        for (int m = 0; m < 4; m++) {
            float4 v = hin[m];
            h[4*m+0] = v.x; h[4*m+1] = v.y; h[4*m+2] = v.z; h[4*m+3] = v.w;
        }
    }
    const float Dd = Ds[k*Dn + d];

    const float2* du = ((const float2*)g_DU) + ((size_t)bk*Ln + (size_t)c*Lc)*Dn + d;
    float* yo = g_ys + ((size_t)bk*Ln + (size_t)c*Lc)*Dn + d;

    float2 ring[4];
    #pragma unroll
    for (int i = 0; i < 4; i++) ring[i] = du[(size_t)i*Dn];
    du += 4*Dn;

    float dA[16];
    #pragma unroll
    for (int n = 0; n < 16; n++) dA[n] = ex2f(ring[0].x * A[n]);

    #pragma unroll 4
    for (int t = 0; t < Lc; t++) {
        float2 cur = ring[t & 3];
        ring[t & 3] = du[0]; du += Dn;
        float dt = cur.x, u = cur.y, dtu = dt*u;
        float pa = 0.f, pb = 0.f;
        #pragma unroll
        for (int m = 0; m < 4; m++) {
            float4 q = sB[t*4 + m];
            float4 r = sC[t*4 + m];
            h[4*m+0] = fmaf(dA[4*m+0], h[4*m+0], dtu*q.x);
            h[4*m+1] = fmaf(dA[4*m+1], h[4*m+1], dtu*q.y);
            h[4*m+2] = fmaf(dA[4*m+2], h[4*m+2], dtu*q.z);
            h[4*m+3] = fmaf(dA[4*m+3], h[4*m+3], dtu*q.w);
            pa = fmaf(h[4*m+0], r.x, pa);
            pb = fmaf(h[4*m+1], r.y, pb);
            pa = fmaf(h[4*m+2], r.z, pa);
            pb = fmaf(h[4*m+3], r.w, pb);
        }
        yo[(size_t)t*Dn] = fmaf(Dd, u, pa + pb);
        float dtn = ring[(t+1) & 3].x;
        #pragma unroll
        for (int n = 0; n < 16; n++) dA[n] = ex2f(dtn * A[n]);
    }
}

// ---------------------------------------------------------------------------
// CrossMerge + LayerNorm.
// ---------------------------------------------------------------------------
__global__ __launch_bounds__(256) void merge_ln_kernel(
    const float* __restrict__ gamma, const float* __restrict__ beta,
    float* __restrict__ out)
{
    const int bid  = blockIdx.x;
    const int b    = bid >> 9;
    const int l    = ((bid & 511) << 3) + (threadIdx.x >> 5);
    const int lane = threadIdx.x & 31;
    const int hh = l >> 6, ww = l & 63;
    const int lT = ww*64 + hh;

    const float* y0 = g_ys + ((size_t)(b*4+0)*Ln + l)*Dn;
    const float* y1 = g_ys + ((size_t)(b*4+1)*Ln + lT)*Dn;
    const float* y2 = g_ys + ((size_t)(b*4+2)*Ln + (4095 - l))*Dn;
    const float* y3 = g_ys + ((size_t)(b*4+3)*Ln + (4095 - lT))*Dn;

    float v[6]; float s = 0.f;
    #pragma unroll
    for (int i = 0; i < 6; i++) {
        int dd = lane + 32*i;
        v[i] = y0[dd] + y1[dd] + y2[dd] + y3[dd];
        s += v[i];
    }
    #pragma unroll
    for (int o = 16; o; o >>= 1) s += __shfl_xor_sync(0xffffffffu, s, o);
    float mean = s * (1.f/192.f);
    float var = 0.f;
    #pragma unroll
    for (int i = 0; i < 6; i++) { float z = v[i] - mean; var = fmaf(z, z, var); }
    #pragma unroll
    for (int o = 16; o; o >>= 1) var += __shfl_xor_sync(0xffffffffu, var, o);
    float rstd = rsqrtf(var*(1.f/192.f) + 1e-5f);

    size_t ob = ((size_t)b*Ln + l)*Dn;
    #pragma unroll
    for (int i = 0; i < 6; i++) {
        int dd = lane + 32*i;
        out[ob + dd] = fmaf((v[i] - mean)*rstd, gamma[dd], beta[dd]);
    }
}

extern "C" void kernel_launch(void* const* d_in, const int* in_sizes, int n_in,
                              void* d_out, int out_size) {
    const float* x    = (const float*)d_in[0];
    const float* xpw  = (const float*)d_in[1];
    const float* dtw  = (const float*)d_in[2];
    const float* dtb  = (const float*)d_in[3];
    const float* Alog = (const float*)d_in[4];
    const float* Ds   = (const float*)d_in[5];
    const float* gam  = (const float*)d_in[6];
    const float* bet  = (const float*)d_in[7];
    float* out = (float*)d_out;

    proj_kernel<<<Bn*Kn*64, 256>>>(x, xpw, dtw, dtb);
    scan_p1<<<32*NC, 192>>>(Alog);
    scan_mid<<<(32*Dn*Nn + 255)/256, 256>>>(Alog);
    scan_p2<<<32*NC, 192>>>(Alog, Ds);
    merge_ln_kernel<<<Bn*512, 256>>>(gam, bet, out);
}